// round 15
// baseline (speedup 1.0000x reference)
#include <cuda_runtime.h>
#include <cuda_fp16.h>

#define BSZ 8
#define LEN 2048
#define HID 1024
#define NH  16
#define HD  64
#define MTOT (BSZ*LEN)      /* 16384 */
#define NKV  (NH*HD)        /* 1024  */
#define MARGIN 2e-3f

#define BM 128
#define BN 128
#define BK 32
#define NITER (HID/BK)          /* 32 */
#define STAGES 3
#define STAGE_BYTES 16384       /* A 8KB + B 8KB */

// ---------------- scratch (device globals; allocation-free rule) ------------
__device__ __half g_V1[(size_t)MTOT * NKV];       // fp16 V1 (quantized store)
__device__ __half g_Ah[(size_t)MTOT * HID];
__device__ __half g_WhV[(size_t)NKV * HID];       // [n][k] K-major
__device__ __half g_WhK[(size_t)NKV * HID];
__device__ unsigned char g_valid[MTOT * NH];
__device__ int2 g_fm[MTOT * NH];
__device__ int2 g_bm[MTOT * NH];
__device__ int g_fixcnt;
__device__ int g_fixlist[MTOT * NH];
__device__ float g_colfix[(size_t)MTOT * NH * 64]; // per-item per-column partial dots

// SW64 swizzle for 64-byte rows (4x 16B chunks): chunk ^= (row>>1)&3
#define SWZ64(row, chunk) ((row) * 64 + (((chunk) ^ (((row) >> 1) & 3)) << 4))

__device__ __forceinline__ unsigned smem_u32(const void* p) {
    unsigned a;
    asm("{ .reg .u64 t; cvta.to.shared.u64 t, %1; cvt.u32.u64 %0, t; }" : "=r"(a) : "l"(p));
    return a;
}
#define LDSM_X4(r0, r1, r2, r3, addr) \
    asm volatile("ldmatrix.sync.aligned.m8n8.x4.shared.b16 {%0,%1,%2,%3},[%4];" \
        : "=r"(r0), "=r"(r1), "=r"(r2), "=r"(r3) : "r"(addr))
#define MMA16816(c, a0, a1, a2, a3, b0, b1) \
    asm volatile("mma.sync.aligned.m16n8k16.row.col.f32.f16.f16.f32 " \
        "{%0,%1,%2,%3},{%4,%5,%6,%7},{%8,%9},{%0,%1,%2,%3};" \
        : "+f"((c)[0]), "+f"((c)[1]), "+f"((c)[2]), "+f"((c)[3]) \
        : "r"(a0), "r"(a1), "r"(a2), "r"(a3), "r"(b0), "r"(b1))
#define CP_ASYNC16(dst, src) \
    asm volatile("cp.async.cg.shared.global [%0], [%1], 16;" :: "r"(dst), "l"(src))
#define CP_COMMIT() asm volatile("cp.async.commit_group;")
#define CP_WAIT1()  asm volatile("cp.async.wait_group 1;")

// ---------------------------------------------------------------------------
// A: f32 -> f16; also zero the fixup counter
__global__ void convA_kernel(const float* __restrict__ hs)
{
    if (blockIdx.x == 0 && threadIdx.x == 0) g_fixcnt = 0;
    const size_t t = (size_t)blockIdx.x * blockDim.x + threadIdx.x;
    const size_t o = t * 8;
    float4 x0 = *(const float4*)(hs + o);
    float4 x1 = *(const float4*)(hs + o + 4);
    float xs[8] = {x0.x, x0.y, x0.z, x0.w, x1.x, x1.y, x1.z, x1.w};
    union { __half b[8]; uint4 u; } h;
    #pragma unroll
    for (int i = 0; i < 8; i++) h.b[i] = __float2half_rn(xs[i]);
    *(uint4*)(g_Ah + o) = h.u;
}

// transpose weights: W[k][n] f32 -> out[n][k] f16
__global__ void convW_kernel(const float* __restrict__ Wv, const float* __restrict__ Wk)
{
    __shared__ float s[32][33];
    const float* W = blockIdx.z ? Wk : Wv;
    __half* O = blockIdx.z ? g_WhK : g_WhV;
    const int kb = blockIdx.x * 32, nb = blockIdx.y * 32;
    const int c = threadIdx.x & 31, r0 = threadIdx.x >> 5;
    #pragma unroll
    for (int j = 0; j < 4; j++) {
        int r = r0 + j * 8;
        s[r][c] = W[(size_t)(kb + r) * NKV + nb + c];
    }
    __syncthreads();
    #pragma unroll
    for (int j = 0; j < 4; j++) {
        int r = r0 + j * 8;
        O[(size_t)(nb + r) * HID + kb + c] = __float2half_rn(s[c][r]);
    }
}

// ---------------------------------------------------------------------------
// HMMA GEMM, fp16 single-product, cp.async 3-stage, BK=32.
// 128 threads, 4 warps (2x2), warp tile 64x64 -> 1.4x less smem fragment BW.
//   grid.x 0..7 : V path      grid.x 8..15 : K path (fused dots + fixlist)
// ---------------------------------------------------------------------------
__global__ __launch_bounds__(128, 2)
void mma_kernel(const float* __restrict__ biasV, const float* __restrict__ biasK,
                const float* __restrict__ RH)
{
    __shared__ __align__(1024) unsigned char smem_buf[STAGES * STAGE_BYTES];
    const unsigned sBase = smem_u32(smem_buf);

    const int tid = threadIdx.x;
    const int lane = tid & 31, wid = tid >> 5;      // 4 warps
    const int warpM = wid & 1, warpN = wid >> 1;    // 2 x 2, warp tile 64x64
    const int z  = blockIdx.x >> 3;
    const int n0 = (blockIdx.x & 7) * BN;
    const int m0 = blockIdx.y * BM;

    const __half* Wh = z ? g_WhK : g_WhV;

    // loader mapping: thread t -> row t, all 4 chunks (A and B)
    unsigned dS[4];
    size_t gOA[4], gOB[4];
    #pragma unroll
    for (int c = 0; c < 4; c++) {
        dS[c]  = SWZ64(tid, c);
        gOA[c] = (size_t)(m0 + tid) * (HID * 2) + c * 16;
        gOB[c] = (size_t)(n0 + tid) * (HID * 2) + c * 16;
    }

    float acc[4][8][4];
    #pragma unroll
    for (int i = 0; i < 4; i++)
        #pragma unroll
        for (int j = 0; j < 8; j++)
            #pragma unroll
            for (int q = 0; q < 4; q++) acc[i][j][q] = 0.f;

    auto issue = [&](int it) {
        const char* aS = (const char*)g_Ah + it * 64;
        const char* bS = (const char*)Wh + it * 64;
        const unsigned st = sBase + (it % STAGES) * STAGE_BYTES;
        #pragma unroll
        for (int c = 0; c < 4; c++) {
            CP_ASYNC16(st + dS[c], aS + gOA[c]);
            CP_ASYNC16(st + 8192 + dS[c], bS + gOB[c]);
        }
    };

    issue(0); CP_COMMIT();
    issue(1); CP_COMMIT();

    // ldsm base addresses (stage 0, ks 0)
    const int aRowBase = warpM * 64 + (lane & 15);
    const int bRowBase = warpN * 64 + (lane & 15);
    const int khalf = lane >> 4;
    unsigned aAd[4], bAd[4];
    #pragma unroll
    for (int mf = 0; mf < 4; mf++) aAd[mf] = sBase + SWZ64(aRowBase + mf * 16, khalf);
    #pragma unroll
    for (int nb = 0; nb < 4; nb++) bAd[nb] = sBase + 8192 + SWZ64(bRowBase + nb * 16, khalf);

    for (int it = 0; it < NITER; it++) {
        CP_WAIT1();
        __syncthreads();
        if (it + 2 < NITER) issue(it + 2);   // stage (it+2)%3 == (it-1)%3: all reads done
        CP_COMMIT();

        const unsigned so = (it % STAGES) * STAGE_BYTES;
        #pragma unroll
        for (int ks = 0; ks < 2; ks++) {
            const unsigned kx = ks ? 0x20u : 0u;   // chunk+2 == XOR 0x20
            unsigned af[4][4], bf[4][4];
            #pragma unroll
            for (int mf = 0; mf < 4; mf++)
                LDSM_X4(af[mf][0], af[mf][1], af[mf][2], af[mf][3], (aAd[mf] + so) ^ kx);
            #pragma unroll
            for (int nb = 0; nb < 4; nb++)
                LDSM_X4(bf[nb][0], bf[nb][1], bf[nb][2], bf[nb][3], (bAd[nb] + so) ^ kx);
            #pragma unroll
            for (int mf = 0; mf < 4; mf++)
                #pragma unroll
                for (int nf = 0; nf < 8; nf++) {
                    unsigned b0 = bf[nf >> 1][(nf & 1) ? 1 : 0];
                    unsigned b1 = bf[nf >> 1][(nf & 1) ? 3 : 2];
                    MMA16816(acc[mf][nf], af[mf][0], af[mf][1], af[mf][2], af[mf][3], b0, b1);
                }
        }
    }

    // ---------------- epilogue ----------------
    const int rBase = m0 + warpM * 64 + (lane >> 2);
    const int cBase = n0 + warpN * 64 + (lane & 3) * 2;

    if (z == 0) {
        #pragma unroll
        for (int mf = 0; mf < 4; mf++) {
            #pragma unroll
            for (int nf = 0; nf < 8; nf++) {
                int col = cBase + nf * 8;
                float b0 = biasV[col], b1 = biasV[col + 1];
                int r0 = rBase + mf * 16;
                __half2 h;
                h = __floats2half2_rn(fmaxf(acc[mf][nf][0] + b0, 0.f),
                                      fmaxf(acc[mf][nf][1] + b1, 0.f));
                *(__half2*)(g_V1 + (size_t)r0 * NKV + col) = h;
                h = __floats2half2_rn(fmaxf(acc[mf][nf][2] + b0, 0.f),
                                      fmaxf(acc[mf][nf][3] + b1, 0.f));
                *(__half2*)(g_V1 + (size_t)(r0 + 8) * NKV + col) = h;
            }
        }
    } else {
        // each warp owns one head (64 cols) x 64 rows: no cross-warp combine
        const int n = (n0 >> 6) + warpN;
        #pragma unroll
        for (int mf = 0; mf < 4; mf++) {
            float slo = 0.f, shi = 0.f;
            #pragma unroll
            for (int nf = 0; nf < 8; nf++) {
                int col = cBase + nf * 8;
                float b0 = biasK[col], b1 = biasK[col + 1];
                float w0 = RH[col],   w1 = RH[col + 1];
                slo += fmaxf(acc[mf][nf][0] + b0, 0.f) * w0
                     + fmaxf(acc[mf][nf][1] + b1, 0.f) * w1;
                shi += fmaxf(acc[mf][nf][2] + b0, 0.f) * w0
                     + fmaxf(acc[mf][nf][3] + b1, 0.f) * w1;
            }
            slo += __shfl_xor_sync(0xffffffffu, slo, 1);
            slo += __shfl_xor_sync(0xffffffffu, slo, 2);
            shi += __shfl_xor_sync(0xffffffffu, shi, 1);
            shi += __shfl_xor_sync(0xffffffffu, shi, 2);
            if ((lane & 3) == 0) {
                float ds[2] = {slo, shi};
                #pragma unroll
                for (int hh = 0; hh < 2; hh++) {
                    int m = rBase + mf * 16 + hh * 8;
                    float dd = ds[hh];
                    int o = m * NH + n;
                    if (fabsf(dd - 0.5f) < MARGIN) {
                        int ix = atomicAdd(&g_fixcnt, 1);
                        g_fixlist[ix] = (m << 4) | n;
                        float* cf = g_colfix + (size_t)ix * 64;
                        #pragma unroll
                        for (int c = 0; c < 64; c++) cf[c] = 0.f;
                        g_valid[o] = 0;
                    } else {
                        g_valid[o] = (dd > 0.5f) ? 1 : 0;
                    }
                }
            }
        }
    }
}

// ---------------------------------------------------------------------------
// fix phase A: 8 blocks per item, each covers a 128-wide k-slice.
// ---------------------------------------------------------------------------
__global__ __launch_bounds__(256)
void fixA_kernel(const float* __restrict__ hs, const float* __restrict__ K1w)
{
    __shared__ float s[4][64];
    const int cnt = g_fixcnt;
    const int tid = threadIdx.x;
    const int col = tid & 63;
    const int kc  = tid >> 6;        // 0..3
    const int slice = blockIdx.x & 7;
    for (int i = blockIdx.x >> 3; i < cnt; i += 512) {
        const int mn = g_fixlist[i];
        const int m = mn >> 4, n = mn & 15;
        const int k0 = slice * 128 + kc * 32;
        const float* a = hs + (size_t)m * HID + k0;
        const float* w = K1w + (size_t)k0 * NKV + n * HD + col;
        float acc = 0.f;
        #pragma unroll 8
        for (int k = 0; k < 32; k++)
            acc = fmaf(a[k], w[(size_t)k * NKV], acc);
        s[kc][col] = acc;
        __syncthreads();
        if (tid < 64)
            atomicAdd(&g_colfix[(size_t)i * 64 + tid],
                      s[0][tid] + s[1][tid] + s[2][tid] + s[3][tid]);
        __syncthreads();
    }
}

// ---------------------------------------------------------------------------
// scan with fused fixB: one block per (b, n).
// ---------------------------------------------------------------------------
__global__ __launch_bounds__(256)
void scan_kernel(const float* __restrict__ K1b, const float* __restrict__ RH)
{
    __shared__ unsigned char sv[LEN];
    __shared__ int pm[LEN];
    __shared__ int sx[LEN];
    __shared__ int tpart[256];
    const int b = blockIdx.x >> 4;
    const int n = blockIdx.x & 15;
    const int tid = threadIdx.x;

    for (int l = tid; l < LEN; l += 256)
        sv[l] = g_valid[(size_t)(b * LEN + l) * NH + n];
    __syncthreads();

    // fixups owned by this (b, n) column
    {
        const int cnt = g_fixcnt;
        for (int i = tid; i < cnt; i += 256) {
            int mn = g_fixlist[i];
            int nn = mn & 15, m = mn >> 4;
            if (nn == n && (m >> 11) == b) {
                const float* cf = g_colfix + (size_t)i * 64;
                float d = 0.f;
                #pragma unroll 8
                for (int c = 0; c < 64; c++)
                    d += fmaxf(cf[c] + K1b[n * HD + c], 0.f) * RH[n * HD + c];
                sv[m & (LEN - 1)] = (d > 0.5f) ? 1 : 0;
            }
        }
    }
    __syncthreads();

    unsigned char v8[8];
    #pragma unroll
    for (int j = 0; j < 8; j++) v8[j] = sv[tid * 8 + j];

    // forward prefix max
    {
        int run = 0, loc[8];
        #pragma unroll
        for (int j = 0; j < 8; j++) {
            int l = tid * 8 + j;
            int a = (v8[j] && l >= 1) ? l : 0;
            run = max(run, a);
            loc[j] = run;
        }
        tpart[tid] = run;
        __syncthreads();
        int acc = tpart[tid];
        #pragma unroll
        for (int of = 1; of < 256; of <<= 1) {
            int o = (tid >= of) ? tpart[tid - of] : 0;
            __syncthreads();
            acc = max(acc, o);
            tpart[tid] = acc;
            __syncthreads();
        }
        int pre = (tid > 0) ? tpart[tid - 1] : 0;
        #pragma unroll
        for (int j = 0; j < 8; j++) pm[tid * 8 + j] = max(pre, loc[j]);
    }
    __syncthreads();
    // backward suffix max (values L-1-l, positions l<=L-2)
    {
        int run = 0, loc[8];
        #pragma unroll
        for (int j = 7; j >= 0; j--) {
            int l = tid * 8 + j;
            int a = (v8[j] && l <= LEN - 2) ? (LEN - 1 - l) : 0;
            run = max(run, a);
            loc[j] = run;
        }
        tpart[tid] = run;
        __syncthreads();
        int acc = tpart[tid];
        #pragma unroll
        for (int of = 1; of < 256; of <<= 1) {
            int o = (tid + of < 256) ? tpart[tid + of] : 0;
            __syncthreads();
            acc = max(acc, o);
            tpart[tid] = acc;
            __syncthreads();
        }
        int suf = (tid < 255) ? tpart[tid + 1] : 0;
        #pragma unroll
        for (int j = 0; j < 8; j++) sx[tid * 8 + j] = max(suf, loc[j]);
    }
    __syncthreads();

    #pragma unroll
    for (int j = 0; j < 8; j++) {
        int l = tid * 8 + j;
        const size_t o = (size_t)(b * LEN + l) * NH + n;
        int fa = pm[l];
        int fb = (fa > 0) ? pm[fa - 1] : 0;
        g_fm[o] = make_int2(fa, fb);
        int s = sx[l];
        int ba, bb;
        if (s == 0) { ba = LEN - 1; bb = LEN - 1; }
        else {
            ba = s;
            int l2 = (LEN - 1) - s;
            int s2 = (l2 + 1 <= LEN - 1) ? sx[l2 + 1] : 0;
            bb = (s2 == 0) ? (LEN - 1) : s2;
        }
        g_bm[o] = make_int2(ba, bb);
    }
}

// ---------------------------------------------------------------------------
// gather from fp16 V1: 4 halves (8B) per row, 4 rows, fp32 weighted sum out.
// ---------------------------------------------------------------------------
__global__ void gather_kernel(const float* __restrict__ bw, float* __restrict__ out)
{
    const int t = blockIdx.x * blockDim.x + threadIdx.x;
    const int h4 = t & 15;
    const int n  = (t >> 4) & 15;
    const int m  = t >> 8;
    if (m >= MTOT) return;
    const int b = m >> 11;
    const size_t io = (size_t)m * NH + n;
    const int2 f  = g_fm[io];
    const int2 bk = g_bm[io];
    const float4 w = *(const float4*)(bw + n * 4);
    const int base = b * LEN;
    const int col = n * HD + h4 * 4;
    const __half2* p0 = (const __half2*)(g_V1 + (size_t)(base + f.x)  * NKV + col);
    const __half2* p1 = (const __half2*)(g_V1 + (size_t)(base + f.y)  * NKV + col);
    const __half2* p2 = (const __half2*)(g_V1 + (size_t)(base + bk.x) * NKV + col);
    const __half2* p3 = (const __half2*)(g_V1 + (size_t)(base + bk.y) * NKV + col);
    float2 a0 = __half22float2(p0[0]), b0 = __half22float2(p0[1]);
    float2 a1 = __half22float2(p1[0]), b1 = __half22float2(p1[1]);
    float2 a2 = __half22float2(p2[0]), b2 = __half22float2(p2[1]);
    float2 a3 = __half22float2(p3[0]), b3 = __half22float2(p3[1]);
    float4 rr;
    rr.x = w.x * a0.x + w.y * a1.x + w.z * a2.x + w.w * a3.x;
    rr.y = w.x * a0.y + w.y * a1.y + w.z * a2.y + w.w * a3.y;
    rr.z = w.x * b0.x + w.y * b1.x + w.z * b2.x + w.w * b3.x;
    rr.w = w.x * b0.y + w.y * b1.y + w.z * b2.y + w.w * b3.y;
    *(float4*)(out + (size_t)m * NKV + col) = rr;
}

// ---------------------------------------------------------------------------
extern "C" void kernel_launch(void* const* d_in, const int* in_sizes, int n_in,
                              void* d_out, int out_size)
{
    const float* hs  = (const float*)d_in[0];
    const float* K1w = (const float*)d_in[1];
    const float* K1b = (const float*)d_in[2];
    const float* V1w = (const float*)d_in[3];
    const float* V1b = (const float*)d_in[4];
    const float* bw  = (const float*)d_in[5];
    const float* RH  = (const float*)d_in[6];
    float* out = (float*)d_out;

    convA_kernel<<<(MTOT * HID / 8) / 256, 256>>>(hs);
    convW_kernel<<<dim3(32, 32, 2), 256>>>(V1w, K1w);
    mma_kernel<<<dim3(16, MTOT / BM), 128>>>(V1b, K1b, RH);
    fixA_kernel<<<4096, 256>>>(hs, K1w);
    scan_kernel<<<BSZ * NH, 256>>>(K1b, RH);
    gather_kernel<<<(MTOT * NH * 16) / 256, 256>>>(bw, out);
}

// round 16
// speedup vs baseline: 1.5641x; 1.5641x over previous
#include <cuda_runtime.h>
#include <cuda_fp16.h>

#define BSZ 8
#define LEN 2048
#define HID 1024
#define NH  16
#define HD  64
#define MTOT (BSZ*LEN)      /* 16384 */
#define NKV  (NH*HD)        /* 1024  */
#define MARGIN 2e-3f

#define BM 128
#define BN 128
#define BK 32
#define NITER (HID/BK)          /* 32 */
#define STAGES 3
#define STAGE_BYTES 16384       /* A 8KB + B 8KB */

#define CONVA_BLOCKS (MTOT * HID / 8 / 256)   /* 8192 */
#define CONVW_BLOCKS 2048                     /* 32x32 tiles x 2 matrices */

// ---------------- scratch (device globals; allocation-free rule) ------------
__device__ __half g_V1[(size_t)MTOT * NKV];       // fp16 V1 (quantized store)
__device__ __half g_Ah[(size_t)MTOT * HID];
__device__ __half g_WhV[(size_t)NKV * HID];       // [n][k] K-major
__device__ __half g_WhK[(size_t)NKV * HID];
__device__ unsigned char g_valid[MTOT * NH];
__device__ int2 g_fm[MTOT * NH];
__device__ int2 g_bm[MTOT * NH];
__device__ int g_fixcnt;
__device__ int g_fixlist[MTOT * NH];
__device__ float g_colfix[(size_t)MTOT * NH * 64]; // per-item per-column partial dots

// SW64 swizzle for 64-byte rows (4x 16B chunks): chunk ^= (row>>1)&3
#define SWZ64(row, chunk) ((row) * 64 + (((chunk) ^ (((row) >> 1) & 3)) << 4))

__device__ __forceinline__ unsigned smem_u32(const void* p) {
    unsigned a;
    asm("{ .reg .u64 t; cvta.to.shared.u64 t, %1; cvt.u32.u64 %0, t; }" : "=r"(a) : "l"(p));
    return a;
}
#define LDSM_X4(r0, r1, r2, r3, addr) \
    asm volatile("ldmatrix.sync.aligned.m8n8.x4.shared.b16 {%0,%1,%2,%3},[%4];" \
        : "=r"(r0), "=r"(r1), "=r"(r2), "=r"(r3) : "r"(addr))
#define MMA16816(c, a0, a1, a2, a3, b0, b1) \
    asm volatile("mma.sync.aligned.m16n8k16.row.col.f32.f16.f16.f32 " \
        "{%0,%1,%2,%3},{%4,%5,%6,%7},{%8,%9},{%0,%1,%2,%3};" \
        : "+f"((c)[0]), "+f"((c)[1]), "+f"((c)[2]), "+f"((c)[3]) \
        : "r"(a0), "r"(a1), "r"(a2), "r"(a3), "r"(b0), "r"(b1))
#define CP_ASYNC16(dst, src) \
    asm volatile("cp.async.cg.shared.global [%0], [%1], 16;" :: "r"(dst), "l"(src))
#define CP_COMMIT() asm volatile("cp.async.commit_group;")
#define CP_WAIT1()  asm volatile("cp.async.wait_group 1;")

// ---------------------------------------------------------------------------
// merged conversion kernel:
//  blocks [0, CONVA_BLOCKS)                 : A f32 -> f16 (8 elems/thread)
//  blocks [CONVA_BLOCKS, +CONVW_BLOCKS)     : W transpose+convert (32x32 tiles)
// ---------------------------------------------------------------------------
__global__ __launch_bounds__(256)
void conv_kernel(const float* __restrict__ hs,
                 const float* __restrict__ Wv, const float* __restrict__ Wk)
{
    if (blockIdx.x < CONVA_BLOCKS) {
        if (blockIdx.x == 0 && threadIdx.x == 0) g_fixcnt = 0;
        const size_t t = (size_t)blockIdx.x * 256 + threadIdx.x;
        const size_t o = t * 8;
        float4 x0 = *(const float4*)(hs + o);
        float4 x1 = *(const float4*)(hs + o + 4);
        float xs[8] = {x0.x, x0.y, x0.z, x0.w, x1.x, x1.y, x1.z, x1.w};
        union { __half b[8]; uint4 u; } h;
        #pragma unroll
        for (int i = 0; i < 8; i++) h.b[i] = __float2half_rn(xs[i]);
        *(uint4*)(g_Ah + o) = h.u;
    } else {
        __shared__ float s[32][33];
        const int id = blockIdx.x - CONVA_BLOCKS;     // 0..2047
        const int zb = id >> 10;                      // 0: V, 1: K
        const int tile = id & 1023;                   // 32x32 grid of tiles
        const float* W = zb ? Wk : Wv;
        __half* O = zb ? g_WhK : g_WhV;
        const int kb = (tile & 31) * 32, nb = (tile >> 5) * 32;
        const int c = threadIdx.x & 31, r0 = threadIdx.x >> 5;
        #pragma unroll
        for (int j = 0; j < 4; j++) {
            int r = r0 + j * 8;
            s[r][c] = W[(size_t)(kb + r) * NKV + nb + c];
        }
        __syncthreads();
        #pragma unroll
        for (int j = 0; j < 4; j++) {
            int r = r0 + j * 8;
            O[(size_t)(nb + r) * HID + kb + c] = __float2half_rn(s[c][r]);
        }
    }
}

// ---------------------------------------------------------------------------
// HMMA GEMM (R10 mainloop), fp16 single-product, cp.async 3-stage, BK=32.
//   grid.x 0..7 : V path      grid.x 8..15 : K path (fused dots + fixlist)
// ---------------------------------------------------------------------------
__global__ __launch_bounds__(256, 2)
void mma_kernel(const float* __restrict__ biasV, const float* __restrict__ biasK,
                const float* __restrict__ RH)
{
    __shared__ __align__(1024) unsigned char smem_buf[STAGES * STAGE_BYTES];
    const unsigned sBase = smem_u32(smem_buf);

    const int tid = threadIdx.x;
    const int lane = tid & 31, wid = tid >> 5;
    const int warpM = wid & 1, warpN = wid >> 1;      // 2 x 4 warps, tile 64x32
    const int z  = blockIdx.x >> 3;
    const int n0 = (blockIdx.x & 7) * BN;
    const int m0 = blockIdx.y * BM;

    const __half* Wh = z ? g_WhK : g_WhV;

    // loader mapping: thread t -> rows (t>>2, t>>2+64), chunk t&3
    const int lr = tid >> 2;
    const int lc = tid & 3;
    const unsigned d0 = SWZ64(lr, lc);
    const unsigned d1 = SWZ64(lr + 64, lc);
    const size_t gA0 = (size_t)(m0 + lr) * (HID * 2) + lc * 16;
    const size_t gA1 = (size_t)(m0 + lr + 64) * (HID * 2) + lc * 16;
    const size_t gB0 = (size_t)(n0 + lr) * (HID * 2) + lc * 16;
    const size_t gB1 = (size_t)(n0 + lr + 64) * (HID * 2) + lc * 16;

    float acc[4][4][4];
    #pragma unroll
    for (int i = 0; i < 4; i++)
        #pragma unroll
        for (int j = 0; j < 4; j++)
            #pragma unroll
            for (int q = 0; q < 4; q++) acc[i][j][q] = 0.f;

    auto issue = [&](int it) {
        const char* aS = (const char*)g_Ah + it * 64;
        const char* bS = (const char*)Wh + it * 64;
        const unsigned st = sBase + (it % STAGES) * STAGE_BYTES;
        CP_ASYNC16(st + d0, aS + gA0);
        CP_ASYNC16(st + d1, aS + gA1);
        CP_ASYNC16(st + 8192 + d0, bS + gB0);
        CP_ASYNC16(st + 8192 + d1, bS + gB1);
    };

    issue(0); CP_COMMIT();
    issue(1); CP_COMMIT();

    // ldsm base addresses (stage 0, ks 0)
    const int aRowBase = warpM * 64 + (lane & 15);
    const int bRowBase = warpN * 32 + (lane & 15);
    const int khalf = lane >> 4;
    unsigned aAd[4], bAd[2];
    #pragma unroll
    for (int mf = 0; mf < 4; mf++) aAd[mf] = sBase + SWZ64(aRowBase + mf * 16, khalf);
    #pragma unroll
    for (int nb = 0; nb < 2; nb++) bAd[nb] = sBase + 8192 + SWZ64(bRowBase + nb * 16, khalf);

    for (int it = 0; it < NITER; it++) {
        CP_WAIT1();
        __syncthreads();
        if (it + 2 < NITER) issue(it + 2);   // stage (it+2)%3 == (it-1)%3: all reads done
        CP_COMMIT();

        const unsigned so = (it % STAGES) * STAGE_BYTES;
        #pragma unroll
        for (int ks = 0; ks < 2; ks++) {
            const unsigned kx = ks ? 0x20u : 0u;   // chunk+2 == XOR 0x20
            unsigned af[4][4], bf[2][4];
            #pragma unroll
            for (int mf = 0; mf < 4; mf++)
                LDSM_X4(af[mf][0], af[mf][1], af[mf][2], af[mf][3], (aAd[mf] + so) ^ kx);
            #pragma unroll
            for (int nb = 0; nb < 2; nb++)
                LDSM_X4(bf[nb][0], bf[nb][1], bf[nb][2], bf[nb][3], (bAd[nb] + so) ^ kx);
            #pragma unroll
            for (int mf = 0; mf < 4; mf++)
                #pragma unroll
                for (int nf = 0; nf < 4; nf++) {
                    unsigned b0 = bf[nf >> 1][(nf & 1) ? 1 : 0];
                    unsigned b1 = bf[nf >> 1][(nf & 1) ? 3 : 2];
                    MMA16816(acc[mf][nf], af[mf][0], af[mf][1], af[mf][2], af[mf][3], b0, b1);
                }
        }
    }

    // ---------------- epilogue ----------------
    const int rBase = m0 + warpM * 64 + (lane >> 2);
    const int cBase = n0 + warpN * 32 + (lane & 3) * 2;

    if (z == 0) {
        #pragma unroll
        for (int mf = 0; mf < 4; mf++) {
            #pragma unroll
            for (int nf = 0; nf < 4; nf++) {
                int col = cBase + nf * 8;
                float b0 = biasV[col], b1 = biasV[col + 1];
                int r0 = rBase + mf * 16;
                __half2 h;
                h = __floats2half2_rn(fmaxf(acc[mf][nf][0] + b0, 0.f),
                                      fmaxf(acc[mf][nf][1] + b1, 0.f));
                *(__half2*)(g_V1 + (size_t)r0 * NKV + col) = h;
                h = __floats2half2_rn(fmaxf(acc[mf][nf][2] + b0, 0.f),
                                      fmaxf(acc[mf][nf][3] + b1, 0.f));
                *(__half2*)(g_V1 + (size_t)(r0 + 8) * NKV + col) = h;
            }
        }
    } else {
        __syncthreads();
        float* sdots = (float*)smem_buf;       // [128][2]
        if (tid < 256) sdots[tid] = 0.f;
        __syncthreads();
        const int hloc = warpN >> 1;
        #pragma unroll
        for (int mf = 0; mf < 4; mf++) {
            float slo = 0.f, shi = 0.f;
            #pragma unroll
            for (int nf = 0; nf < 4; nf++) {
                int col = cBase + nf * 8;
                float b0 = biasK[col], b1 = biasK[col + 1];
                float w0 = RH[col],   w1 = RH[col + 1];
                slo += fmaxf(acc[mf][nf][0] + b0, 0.f) * w0
                     + fmaxf(acc[mf][nf][1] + b1, 0.f) * w1;
                shi += fmaxf(acc[mf][nf][2] + b0, 0.f) * w0
                     + fmaxf(acc[mf][nf][3] + b1, 0.f) * w1;
            }
            slo += __shfl_xor_sync(0xffffffffu, slo, 1);
            slo += __shfl_xor_sync(0xffffffffu, slo, 2);
            shi += __shfl_xor_sync(0xffffffffu, shi, 1);
            shi += __shfl_xor_sync(0xffffffffu, shi, 2);
            if ((lane & 3) == 0) {
                int rloc = warpM * 64 + mf * 16 + (lane >> 2);
                atomicAdd(&sdots[rloc * 2 + hloc], slo);
                atomicAdd(&sdots[(rloc + 8) * 2 + hloc], shi);
            }
        }
        __syncthreads();
        if (tid < 256) {
            int rloc = tid >> 1, h = tid & 1;
            int m = m0 + rloc;
            int n = (n0 >> 6) + h;
            float dd = sdots[tid];
            int o = m * NH + n;
            if (fabsf(dd - 0.5f) < MARGIN) {
                int ix = atomicAdd(&g_fixcnt, 1);
                g_fixlist[ix] = (m << 4) | n;
                float* cf = g_colfix + (size_t)ix * 64;
                #pragma unroll
                for (int c = 0; c < 64; c++) cf[c] = 0.f;
                g_valid[o] = 0;
            } else {
                g_valid[o] = (dd > 0.5f) ? 1 : 0;
            }
        }
    }
}

// ---------------------------------------------------------------------------
// fix phase A: 8 blocks per item, each covers a 128-wide k-slice.
// ---------------------------------------------------------------------------
__global__ __launch_bounds__(256)
void fixA_kernel(const float* __restrict__ hs, const float* __restrict__ K1w)
{
    __shared__ float s[4][64];
    const int cnt = g_fixcnt;
    const int tid = threadIdx.x;
    const int col = tid & 63;
    const int kc  = tid >> 6;        // 0..3
    const int slice = blockIdx.x & 7;
    for (int i = blockIdx.x >> 3; i < cnt; i += 512) {
        const int mn = g_fixlist[i];
        const int m = mn >> 4, n = mn & 15;
        const int k0 = slice * 128 + kc * 32;
        const float* a = hs + (size_t)m * HID + k0;
        const float* w = K1w + (size_t)k0 * NKV + n * HD + col;
        float acc = 0.f;
        #pragma unroll 8
        for (int k = 0; k < 32; k++)
            acc = fmaf(a[k], w[(size_t)k * NKV], acc);
        s[kc][col] = acc;
        __syncthreads();
        if (tid < 64)
            atomicAdd(&g_colfix[(size_t)i * 64 + tid],
                      s[0][tid] + s[1][tid] + s[2][tid] + s[3][tid]);
        __syncthreads();
    }
}

// fix phase B: warp per item — bias+relu+RH dot, threshold, write valid.
__global__ __launch_bounds__(256)
void fixB_kernel(const float* __restrict__ K1b, const float* __restrict__ RH)
{
    const int cnt = g_fixcnt;
    const int w = blockIdx.x * 8 + (threadIdx.x >> 5);
    const int lane = threadIdx.x & 31;
    const int nw = gridDim.x * 8;
    for (int i = w; i < cnt; i += nw) {
        const int mn = g_fixlist[i];
        const int m = mn >> 4, n = mn & 15;
        const float* cf = g_colfix + (size_t)i * 64;
        float d = fmaxf(cf[lane] + K1b[n * HD + lane], 0.f) * RH[n * HD + lane]
                + fmaxf(cf[lane + 32] + K1b[n * HD + lane + 32], 0.f) * RH[n * HD + lane + 32];
        #pragma unroll
        for (int o = 16; o; o >>= 1) d += __shfl_xor_sync(0xffffffffu, d, o);
        if (lane == 0) g_valid[m * NH + n] = (d > 0.5f) ? 1 : 0;
    }
}

// ---------------------------------------------------------------------------
// parallel scan via prefix/suffix max (exact reference semantics)
// ---------------------------------------------------------------------------
__global__ __launch_bounds__(256)
void scan_kernel()
{
    __shared__ int pm[LEN];
    __shared__ int sx[LEN];
    __shared__ int tpart[256];
    const int b = blockIdx.x >> 4;
    const int n = blockIdx.x & 15;
    const int tid = threadIdx.x;

    unsigned char v8[8];
    #pragma unroll
    for (int j = 0; j < 8; j++)
        v8[j] = g_valid[(size_t)(b * LEN + tid * 8 + j) * NH + n];

    // forward prefix max
    {
        int run = 0, loc[8];
        #pragma unroll
        for (int j = 0; j < 8; j++) {
            int l = tid * 8 + j;
            int a = (v8[j] && l >= 1) ? l : 0;
            run = max(run, a);
            loc[j] = run;
        }
        tpart[tid] = run;
        __syncthreads();
        int acc = tpart[tid];
        #pragma unroll
        for (int of = 1; of < 256; of <<= 1) {
            int o = (tid >= of) ? tpart[tid - of] : 0;
            __syncthreads();
            acc = max(acc, o);
            tpart[tid] = acc;
            __syncthreads();
        }
        int pre = (tid > 0) ? tpart[tid - 1] : 0;
        #pragma unroll
        for (int j = 0; j < 8; j++) pm[tid * 8 + j] = max(pre, loc[j]);
    }
    __syncthreads();
    // backward suffix max (values L-1-l, positions l<=L-2)
    {
        int run = 0, loc[8];
        #pragma unroll
        for (int j = 7; j >= 0; j--) {
            int l = tid * 8 + j;
            int a = (v8[j] && l <= LEN - 2) ? (LEN - 1 - l) : 0;
            run = max(run, a);
            loc[j] = run;
        }
        tpart[tid] = run;
        __syncthreads();
        int acc = tpart[tid];
        #pragma unroll
        for (int of = 1; of < 256; of <<= 1) {
            int o = (tid + of < 256) ? tpart[tid + of] : 0;
            __syncthreads();
            acc = max(acc, o);
            tpart[tid] = acc;
            __syncthreads();
        }
        int suf = (tid < 255) ? tpart[tid + 1] : 0;
        #pragma unroll
        for (int j = 0; j < 8; j++) sx[tid * 8 + j] = max(suf, loc[j]);
    }
    __syncthreads();

    #pragma unroll
    for (int j = 0; j < 8; j++) {
        int l = tid * 8 + j;
        const size_t o = (size_t)(b * LEN + l) * NH + n;
        int fa = pm[l];
        int fb = (fa > 0) ? pm[fa - 1] : 0;
        g_fm[o] = make_int2(fa, fb);
        int s = sx[l];
        int ba, bb;
        if (s == 0) { ba = LEN - 1; bb = LEN - 1; }
        else {
            ba = s;
            int l2 = (LEN - 1) - s;
            int s2 = (l2 + 1 <= LEN - 1) ? sx[l2 + 1] : 0;
            bb = (s2 == 0) ? (LEN - 1) : s2;
        }
        g_bm[o] = make_int2(ba, bb);
    }
}

// ---------------------------------------------------------------------------
// gather from fp16 V1: 4 halves (8B) per row, 4 rows, fp32 weighted sum out.
// ---------------------------------------------------------------------------
__global__ void gather_kernel(const float* __restrict__ bw, float* __restrict__ out)
{
    const int t = blockIdx.x * blockDim.x + threadIdx.x;
    const int h4 = t & 15;
    const int n  = (t >> 4) & 15;
    const int m  = t >> 8;
    if (m >= MTOT) return;
    const int b = m >> 11;
    const size_t io = (size_t)m * NH + n;
    const int2 f  = g_fm[io];
    const int2 bk = g_bm[io];
    const float4 w = *(const float4*)(bw + n * 4);
    const int base = b * LEN;
    const int col = n * HD + h4 * 4;
    const __half2* p0 = (const __half2*)(g_V1 + (size_t)(base + f.x)  * NKV + col);
    const __half2* p1 = (const __half2*)(g_V1 + (size_t)(base + f.y)  * NKV + col);
    const __half2* p2 = (const __half2*)(g_V1 + (size_t)(base + bk.x) * NKV + col);
    const __half2* p3 = (const __half2*)(g_V1 + (size_t)(base + bk.y) * NKV + col);
    float2 a0 = __half22float2(p0[0]), b0 = __half22float2(p0[1]);
    float2 a1 = __half22float2(p1[0]), b1 = __half22float2(p1[1]);
    float2 a2 = __half22float2(p2[0]), b2 = __half22float2(p2[1]);
    float2 a3 = __half22float2(p3[0]), b3 = __half22float2(p3[1]);
    float4 rr;
    rr.x = w.x * a0.x + w.y * a1.x + w.z * a2.x + w.w * a3.x;
    rr.y = w.x * a0.y + w.y * a1.y + w.z * a2.y + w.w * a3.y;
    rr.z = w.x * b0.x + w.y * b1.x + w.z * b2.x + w.w * b3.x;
    rr.w = w.x * b0.y + w.y * b1.y + w.z * b2.y + w.w * b3.y;
    *(float4*)(out + (size_t)m * NKV + col) = rr;
}

// ---------------------------------------------------------------------------
extern "C" void kernel_launch(void* const* d_in, const int* in_sizes, int n_in,
                              void* d_out, int out_size)
{
    const float* hs  = (const float*)d_in[0];
    const float* K1w = (const float*)d_in[1];
    const float* K1b = (const float*)d_in[2];
    const float* V1w = (const float*)d_in[3];
    const float* V1b = (const float*)d_in[4];
    const float* bw  = (const float*)d_in[5];
    const float* RH  = (const float*)d_in[6];
    float* out = (float*)d_out;

    conv_kernel<<<CONVA_BLOCKS + CONVW_BLOCKS, 256>>>(hs, V1w, K1w);
    mma_kernel<<<dim3(16, MTOT / BM), 256>>>(V1b, K1b, RH);
    fixA_kernel<<<4096, 256>>>(hs, K1w);
    fixB_kernel<<<64, 256>>>(K1b, RH);
    scan_kernel<<<BSZ * NH, 256>>>();
    gather_kernel<<<(MTOT * NH * 16) / 256, 256>>>(bw, out);
}